// round 12
// baseline (speedup 1.0000x reference)
#include <cuda_runtime.h>

#define TPB    128
#define ROWS   64
#define ST     68          // row stride (floats); 68 % 32 == 4
#define NSTEPS 16

#define M_ST     0
#define M_GELU   1
#define M_ADDLN  2
#define M_LNGELU 3

__device__ float g_Wca[64 * 64];
__device__ float g_bca[64];

__device__ __forceinline__ float gelu_exact(float v) {
    return 0.5f * v * (1.0f + erff(v * 0.70710678118654752f));
}
__device__ __forceinline__ void ffma2(unsigned long long& acc,
                                      unsigned long long a, unsigned long long b) {
    asm("fma.rn.f32x2 %0, %1, %2, %0;" : "+l"(acc) : "l"(a), "l"(b));
}
__device__ __forceinline__ float pairsum(unsigned long long v) {
    float lo, hi;
    asm("mov.b64 {%0, %1}, %2;" : "=f"(lo), "=f"(hi) : "l"(v));
    return lo + hi;
}

// ---------------------------------------------------------------------------
// epi: shared epilogue. Row rbase+4i fully inside warp across lx (shfl 4,8,16).
// M_ADDLN: v += dest, LayerNorm, store. M_LNGELU: LN then gelu. NI rows/lane.
// ---------------------------------------------------------------------------
template<int MODE, int NI>
__device__ __forceinline__ void epi(float (&v)[NI][8], float* sOut, int rbase, int c0,
                                    const float* __restrict__ lg,
                                    const float* __restrict__ lb)
{
    if (MODE == M_ADDLN) {
#pragma unroll
        for (int i = 0; i < NI; i++) {
            const float* op = sOut + (rbase + 4 * i) * ST + c0;
            float4 d0 = *(const float4*)op;
            float4 d1 = *(const float4*)(op + 4);
            v[i][0] += d0.x; v[i][1] += d0.y; v[i][2] += d0.z; v[i][3] += d0.w;
            v[i][4] += d1.x; v[i][5] += d1.y; v[i][6] += d1.z; v[i][7] += d1.w;
        }
    }
    if (MODE == M_ADDLN || MODE == M_LNGELU) {
        float4 g0 = __ldg((const float4*)(lg + c0));
        float4 g1 = __ldg((const float4*)(lg + c0 + 4));
        float4 b0 = __ldg((const float4*)(lb + c0));
        float4 b1 = __ldg((const float4*)(lb + c0 + 4));
#pragma unroll
        for (int i = 0; i < NI; i++) {
            float s = 0.f, ss = 0.f;
#pragma unroll
            for (int j = 0; j < 8; j++) { s += v[i][j]; ss = fmaf(v[i][j], v[i][j], ss); }
            s += __shfl_xor_sync(0xFFFFFFFFu, s, 4);  ss += __shfl_xor_sync(0xFFFFFFFFu, ss, 4);
            s += __shfl_xor_sync(0xFFFFFFFFu, s, 8);  ss += __shfl_xor_sync(0xFFFFFFFFu, ss, 8);
            s += __shfl_xor_sync(0xFFFFFFFFu, s, 16); ss += __shfl_xor_sync(0xFFFFFFFFu, ss, 16);
            float m = s * (1.0f / 64.0f);
            float inv = rsqrtf(ss * (1.0f / 64.0f) - m * m + 1e-5f);
            v[i][0] = (v[i][0] - m) * inv * g0.x + b0.x;
            v[i][1] = (v[i][1] - m) * inv * g0.y + b0.y;
            v[i][2] = (v[i][2] - m) * inv * g0.z + b0.z;
            v[i][3] = (v[i][3] - m) * inv * g0.w + b0.w;
            v[i][4] = (v[i][4] - m) * inv * g1.x + b1.x;
            v[i][5] = (v[i][5] - m) * inv * g1.y + b1.y;
            v[i][6] = (v[i][6] - m) * inv * g1.z + b1.z;
            v[i][7] = (v[i][7] - m) * inv * g1.w + b1.w;
        }
    }
    if (MODE == M_GELU || MODE == M_LNGELU) {
#pragma unroll
        for (int i = 0; i < NI; i++)
#pragma unroll
            for (int j = 0; j < 8; j++) v[i][j] = gelu_exact(v[i][j]);
    }
#pragma unroll
    for (int i = 0; i < NI; i++) {
        float* op = sOut + (rbase + 4 * i) * ST + c0;
        *(float4*)op       = make_float4(v[i][0], v[i][1], v[i][2], v[i][3]);
        *(float4*)(op + 4) = make_float4(v[i][4], v[i][5], v[i][6], v[i][7]);
    }
}

// ---------------------------------------------------------------------------
// gemmRS: one warp = rows [32rw, 32rw+32) x all 64 cols, K=64.
// lane: ly=lane&3 (rows 32rw+ly+4i, i<8), lx=lane>>2 (cols 8lx..8lx+7).
// ---------------------------------------------------------------------------
template<int MODE>
__device__ __forceinline__ void gemmRS(const float* sIn, const float* __restrict__ W,
                                       const float* __restrict__ bias, float* sOut,
                                       int rw, int lane,
                                       const float* __restrict__ lg = nullptr,
                                       const float* __restrict__ lb = nullptr)
{
    const int ly = lane & 3, lx = lane >> 2;
    const int rbase = 32 * rw + ly;
    const int c0 = 8 * lx;
    unsigned long long acc[8][8];
#pragma unroll
    for (int i = 0; i < 8; i++)
#pragma unroll
        for (int j = 0; j < 8; j++) acc[i][j] = 0ull;

    const float* ip = sIn + rbase * ST;
    const float* wp = W + c0 * 64;
#pragma unroll 1
    for (int k = 0; k < 64; k += 4) {
        ulonglong2 w[8];
#pragma unroll
        for (int j = 0; j < 8; j++) w[j] = __ldg((const ulonglong2*)(wp + j * 64 + k));
#pragma unroll
        for (int i = 0; i < 8; i++) {
            ulonglong2 b = *(const ulonglong2*)(ip + i * (4 * ST) + k);
#pragma unroll
            for (int j = 0; j < 8; j++) {
                ffma2(acc[i][j], w[j].x, b.x);
                ffma2(acc[i][j], w[j].y, b.y);
            }
        }
    }
    float4 bb0 = __ldg((const float4*)(bias + c0));
    float4 bb1 = __ldg((const float4*)(bias + c0 + 4));
    float v[8][8];
#pragma unroll
    for (int i = 0; i < 8; i++) {
        v[i][0] = pairsum(acc[i][0]) + bb0.x; v[i][1] = pairsum(acc[i][1]) + bb0.y;
        v[i][2] = pairsum(acc[i][2]) + bb0.z; v[i][3] = pairsum(acc[i][3]) + bb0.w;
        v[i][4] = pairsum(acc[i][4]) + bb1.x; v[i][5] = pairsum(acc[i][5]) + bb1.y;
        v[i][6] = pairsum(acc[i][6]) + bb1.z; v[i][7] = pairsum(acc[i][7]) + bb1.w;
    }
    epi<MODE, 8>(v, sOut, rbase, c0, lg, lb);
}

// ---------------------------------------------------------------------------
// gemmQ: 4-warp single unit; warp w = rows [16w, 16w+16) x all 64 cols, K=64.
// ---------------------------------------------------------------------------
template<int MODE>
__device__ __forceinline__ void gemmQ(const float* sIn, const float* __restrict__ W,
                                      const float* __restrict__ bias, float* sOut,
                                      int w, int lane,
                                      const float* __restrict__ lg = nullptr,
                                      const float* __restrict__ lb = nullptr)
{
    const int ly = lane & 3, lx = lane >> 2;
    const int rbase = 16 * w + ly;
    const int c0 = 8 * lx;
    unsigned long long acc[4][8];
#pragma unroll
    for (int i = 0; i < 4; i++)
#pragma unroll
        for (int j = 0; j < 8; j++) acc[i][j] = 0ull;

    const float* ip = sIn + rbase * ST;
    const float* wp = W + c0 * 64;
#pragma unroll 1
    for (int k = 0; k < 64; k += 4) {
        ulonglong2 w4[8];
#pragma unroll
        for (int j = 0; j < 8; j++) w4[j] = __ldg((const ulonglong2*)(wp + j * 64 + k));
#pragma unroll
        for (int i = 0; i < 4; i++) {
            ulonglong2 b = *(const ulonglong2*)(ip + i * (4 * ST) + k);
#pragma unroll
            for (int j = 0; j < 8; j++) {
                ffma2(acc[i][j], w4[j].x, b.x);
                ffma2(acc[i][j], w4[j].y, b.y);
            }
        }
    }
    float4 bb0 = __ldg((const float4*)(bias + c0));
    float4 bb1 = __ldg((const float4*)(bias + c0 + 4));
    float v[4][8];
#pragma unroll
    for (int i = 0; i < 4; i++) {
        v[i][0] = pairsum(acc[i][0]) + bb0.x; v[i][1] = pairsum(acc[i][1]) + bb0.y;
        v[i][2] = pairsum(acc[i][2]) + bb0.z; v[i][3] = pairsum(acc[i][3]) + bb0.w;
        v[i][4] = pairsum(acc[i][4]) + bb1.x; v[i][5] = pairsum(acc[i][5]) + bb1.y;
        v[i][6] = pairsum(acc[i][6]) + bb1.z; v[i][7] = pairsum(acc[i][7]) + bb1.w;
    }
    epi<MODE, 4>(v, sOut, rbase, c0, lg, lb);
}

// FFN second layer: K=128 from two 64-col buffers; W row stride 128; add+LN.
__device__ __forceinline__ void gemmQ128(const float* sA, const float* sB,
                                         const float* __restrict__ W,
                                         const float* __restrict__ bias, float* sOut,
                                         int w, int lane,
                                         const float* __restrict__ lg,
                                         const float* __restrict__ lb)
{
    const int ly = lane & 3, lx = lane >> 2;
    const int rbase = 16 * w + ly;
    const int c0 = 8 * lx;
    unsigned long long acc[4][8];
#pragma unroll
    for (int i = 0; i < 4; i++)
#pragma unroll
        for (int j = 0; j < 8; j++) acc[i][j] = 0ull;

    const float* wp = W + c0 * 128;
#pragma unroll 1
    for (int k = 0; k < 64; k += 4) {
        ulonglong2 w4[8];
#pragma unroll
        for (int j = 0; j < 8; j++) w4[j] = __ldg((const ulonglong2*)(wp + j * 128 + k));
        const float* ip = sA + rbase * ST;
#pragma unroll
        for (int i = 0; i < 4; i++) {
            ulonglong2 b = *(const ulonglong2*)(ip + i * (4 * ST) + k);
#pragma unroll
            for (int j = 0; j < 8; j++) {
                ffma2(acc[i][j], w4[j].x, b.x);
                ffma2(acc[i][j], w4[j].y, b.y);
            }
        }
    }
#pragma unroll 1
    for (int k = 0; k < 64; k += 4) {
        ulonglong2 w4[8];
#pragma unroll
        for (int j = 0; j < 8; j++) w4[j] = __ldg((const ulonglong2*)(wp + j * 128 + 64 + k));
        const float* ip = sB + rbase * ST;
#pragma unroll
        for (int i = 0; i < 4; i++) {
            ulonglong2 b = *(const ulonglong2*)(ip + i * (4 * ST) + k);
#pragma unroll
            for (int j = 0; j < 8; j++) {
                ffma2(acc[i][j], w4[j].x, b.x);
                ffma2(acc[i][j], w4[j].y, b.y);
            }
        }
    }
    float4 bb0 = __ldg((const float4*)(bias + c0));
    float4 bb1 = __ldg((const float4*)(bias + c0 + 4));
    float v[4][8];
#pragma unroll
    for (int i = 0; i < 4; i++) {
        v[i][0] = pairsum(acc[i][0]) + bb0.x; v[i][1] = pairsum(acc[i][1]) + bb0.y;
        v[i][2] = pairsum(acc[i][2]) + bb0.z; v[i][3] = pairsum(acc[i][3]) + bb0.w;
        v[i][4] = pairsum(acc[i][4]) + bb1.x; v[i][5] = pairsum(acc[i][5]) + bb1.y;
        v[i][6] = pairsum(acc[i][6]) + bb1.z; v[i][7] = pairsum(acc[i][7]) + bb1.w;
    }
    epi<M_ADDLN, 4>(v, sOut, rbase, c0, lg, lb);
}

// Prologue: K=200 from global x; LN+gelu fused.
__device__ __forceinline__ void gemmP(const float* __restrict__ xg,
                                      const float* __restrict__ W,
                                      const float* __restrict__ bias, float* sOut,
                                      int w, int lane,
                                      const float* __restrict__ lg,
                                      const float* __restrict__ lb)
{
    const int ly = lane & 3, lx = lane >> 2;
    const int rbase = 16 * w + ly;
    const int c0 = 8 * lx;
    unsigned long long acc[4][8];
#pragma unroll
    for (int i = 0; i < 4; i++)
#pragma unroll
        for (int j = 0; j < 8; j++) acc[i][j] = 0ull;

    const float* ip = xg + (size_t)rbase * 200;
    const float* wp = W + c0 * 200;
#pragma unroll 1
    for (int k = 0; k < 200; k += 4) {
        ulonglong2 w4[8];
#pragma unroll
        for (int j = 0; j < 8; j++) w4[j] = __ldg((const ulonglong2*)(wp + j * 200 + k));
#pragma unroll
        for (int i = 0; i < 4; i++) {
            ulonglong2 b = __ldg((const ulonglong2*)(ip + (size_t)i * 4 * 200 + k));
#pragma unroll
            for (int j = 0; j < 8; j++) {
                ffma2(acc[i][j], w4[j].x, b.x);
                ffma2(acc[i][j], w4[j].y, b.y);
            }
        }
    }
    float4 bb0 = __ldg((const float4*)(bias + c0));
    float4 bb1 = __ldg((const float4*)(bias + c0 + 4));
    float v[4][8];
#pragma unroll
    for (int i = 0; i < 4; i++) {
        v[i][0] = pairsum(acc[i][0]) + bb0.x; v[i][1] = pairsum(acc[i][1]) + bb0.y;
        v[i][2] = pairsum(acc[i][2]) + bb0.z; v[i][3] = pairsum(acc[i][3]) + bb0.w;
        v[i][4] = pairsum(acc[i][4]) + bb1.x; v[i][5] = pairsum(acc[i][5]) + bb1.y;
        v[i][6] = pairsum(acc[i][6]) + bb1.z; v[i][7] = pairsum(acc[i][7]) + bb1.w;
    }
    epi<M_LNGELU, 4>(v, sOut, rbase, c0, lg, lb);
}

// prep: W_ca = y_out_w @ Wvy ; b_ca = y_out_w @ bvy + y_out_b
__global__ void prep_kernel(const float* __restrict__ y_out_w,
                            const float* __restrict__ y_in_w,
                            const float* __restrict__ y_in_b,
                            const float* __restrict__ y_out_b)
{
    int i = blockIdx.x;
    int k = threadIdx.x;
    const float* Wvy = y_in_w + 128 * 64;
    float a = 0.f;
    for (int j = 0; j < 64; j++)
        a = fmaf(y_out_w[i * 64 + j], Wvy[j * 64 + k], a);
    g_Wca[i * 64 + k] = a;
    if (k == 0) {
        float b = y_out_b[i];
        for (int j = 0; j < 64; j++) b = fmaf(y_out_w[i * 64 + j], y_in_b[128 + j], b);
        g_bca[i] = b;
    }
}

#define PAIR(MODE, inA, WA, bA, oA, inB, WB, bB, oB) do {               \
    if (wid < 2) gemmRS<MODE>((inA), (WA), (bA), (oA), wid, lane);      \
    else         gemmRS<MODE>((inB), (WB), (bB), (oB), wid - 2, lane);  \
    __syncthreads(); } while (0)

__global__ void __launch_bounds__(TPB, 2)
trm_kernel(const float* __restrict__ x,
           const float* __restrict__ W_in,     const float* __restrict__ b_in,
           const float* __restrict__ g_in,     const float* __restrict__ be_in,
           const float* __restrict__ z_in_w,   const float* __restrict__ z_in_b,
           const float* __restrict__ z_out_w,  const float* __restrict__ z_out_b,
           const float* __restrict__ z_ffn_w1, const float* __restrict__ z_ffn_b1,
           const float* __restrict__ z_ffn_w2, const float* __restrict__ z_ffn_b2,
           const float* __restrict__ zn1_g,    const float* __restrict__ zn1_b,
           const float* __restrict__ zn2_g,    const float* __restrict__ zn2_b,
           const float* __restrict__ y_ffn_w1, const float* __restrict__ y_ffn_b1,
           const float* __restrict__ y_ffn_w2, const float* __restrict__ y_ffn_b2,
           const float* __restrict__ yn1_g,    const float* __restrict__ yn1_b,
           const float* __restrict__ yn2_g,    const float* __restrict__ yn2_b,
           const float* __restrict__ W_out,    const float* __restrict__ b_out,
           float* __restrict__ out, int Btotal)
{
    extern __shared__ float sm[];
    float* sKX = sm + 0 * ROWS * ST;
    float* sVX = sm + 1 * ROWS * ST;
    float* sY  = sm + 2 * ROWS * ST;
    float* sZ  = sm + 3 * ROWS * ST;
    float* sSA = sm + 4 * ROWS * ST;
    float* sSB = sm + 5 * ROWS * ST;

    const int tid  = threadIdx.x;
    const int wid  = tid >> 5;
    const int lane = tid & 31;
    const int row0 = blockIdx.x * ROWS;
    const int erow = tid >> 1, eh = tid & 1;        // 2 threads/row elementwise
    const int eoff = erow * ST + 32 * eh;

    const float* Wq = z_in_w;
    const float* Wk = z_in_w + 64 * 64;
    const float* Wv = z_in_w + 128 * 64;
    const float* bq = z_in_b;
    const float* bk = z_in_b + 64;
    const float* bv = z_in_b + 128;

    // ---- prologue: x_proj = gelu(LN(x @ W_in^T + b_in)) -> SA (fused) ----
    gemmP(x + (size_t)row0 * 200, W_in, b_in, sSA, wid, lane, g_in, be_in);
    __syncthreads();
    // kx || vx
    PAIR(M_ST, sSA, Wk, bk, sKX,  sSA, Wv, bv, sVX);
    // zero y, z
    {
        float* yp = sY + eoff;
        float* zp = sZ + eoff;
        const float4 zz = make_float4(0.f, 0.f, 0.f, 0.f);
#pragma unroll
        for (int i = 0; i < 8; i++) { *(float4*)(yp + 4*i) = zz; *(float4*)(zp + 4*i) = zz; }
    }
    __syncthreads();

    // ---- 16 recursion steps ----
#pragma unroll 1
    for (int s = 0; s < NSTEPS; s++) {
        float qv[32];
        float s0[2], s2[2], wa0[2], wa1[2], wa2[2];

        // P1: q(z) -> SA || k(z) -> SB
        PAIR(M_ST, sZ, Wq, bq, sSA,  sZ, Wk, bk, sSB);
        // E1: q -> regs; s0 = q.kx, s2 = q.kz
        {
            const float4* qp  = (const float4*)(sSA + eoff);
            const float4* kxp = (const float4*)(sKX + eoff);
            const float4* kzp = (const float4*)(sSB + eoff);
            s0[0] = s0[1] = s2[0] = s2[1] = 0.f;
#pragma unroll
            for (int i = 0; i < 8; i++) {
                float4 t = qp[i];
                qv[4*i] = t.x; qv[4*i+1] = t.y; qv[4*i+2] = t.z; qv[4*i+3] = t.w;
                int hh = i >> 2;
                float4 a = kxp[i];
                float4 c = kzp[i];
                s0[hh] = fmaf(t.x, a.x, fmaf(t.y, a.y, fmaf(t.z, a.z, fmaf(t.w, a.w, s0[hh]))));
                s2[hh] = fmaf(t.x, c.x, fmaf(t.y, c.y, fmaf(t.z, c.z, fmaf(t.w, c.w, s2[hh]))));
            }
        }
        __syncthreads();
        // P2: k(y) -> SB (q stays in registers)
        gemmQ<M_ST>(sY, Wk, bk, sSB, wid, lane);
        __syncthreads();
        // E2: s1 = q.ky ; softmax
        {
            const float4* kyp = (const float4*)(sSB + eoff);
            float s1[2] = {0.f, 0.f};
#pragma unroll
            for (int i = 0; i < 8; i++) {
                int hh = i >> 2;
                float4 a = kyp[i];
                s1[hh] = fmaf(qv[4*i], a.x, fmaf(qv[4*i+1], a.y,
                         fmaf(qv[4*i+2], a.z, fmaf(qv[4*i+3], a.w, s1[hh]))));
            }
#pragma unroll
            for (int hh = 0; hh < 2; hh++) {
                float a0 = s0[hh] * 0.25f, a1 = s1[hh] * 0.25f, a2 = s2[hh] * 0.25f;
                float mx = fmaxf(a0, fmaxf(a1, a2));
                float e0 = __expf(a0 - mx), e1 = __expf(a1 - mx), e2 = __expf(a2 - mx);
                float rs = 1.0f / (e0 + e1 + e2);
                wa0[hh] = e0 * rs; wa1[hh] = e1 * rs; wa2[hh] = e2 * rs;
            }
        }
        __syncthreads();
        // P3: v(y) -> SA || v(z) -> SB
        PAIR(M_ST, sY, Wv, bv, sSA,  sZ, Wv, bv, sSB);
        // E3: SA := wa0*vx + wa1*vy(SA) + wa2*vz(SB)
        {
            float* sap = sSA + eoff;
            const float4* sbp = (const float4*)(sSB + eoff);
            const float4* vxp = (const float4*)(sVX + eoff);
#pragma unroll
            for (int i = 0; i < 8; i++) {
                int hh = i >> 2;
                float4 a = vxp[i];
                float4 b2 = *(const float4*)(sap + 4*i);
                float4 c = sbp[i];
                float4 o;
                o.x = wa0[hh]*a.x + wa1[hh]*b2.x + wa2[hh]*c.x;
                o.y = wa0[hh]*a.y + wa1[hh]*b2.y + wa2[hh]*c.y;
                o.z = wa0[hh]*a.z + wa1[hh]*b2.z + wa2[hh]*c.z;
                o.w = wa0[hh]*a.w + wa1[hh]*b2.w + wa2[hh]*c.w;
                *(float4*)(sap + 4*i) = o;
            }
        }
        __syncthreads();
        // P4: z = LN(z + SA @ z_out^T + b)   [LN fused]
        gemmQ<M_ADDLN>(sSA, z_out_w, z_out_b, sZ, wid, lane, zn1_g, zn1_b);
        __syncthreads();
        // P5: FFN z hidden (gelu fused): dims 0-63 -> SA || 64-127 -> SB
        PAIR(M_GELU, sZ, z_ffn_w1, z_ffn_b1, sSA,  sZ, z_ffn_w1 + 64*64, z_ffn_b1 + 64, sSB);
        // P6: z = LN(z + [SA|SB] @ w2^T + b2)   [LN fused]
        gemmQ128(sSA, sSB, z_ffn_w2, z_ffn_b2, sZ, wid, lane, zn2_g, zn2_b);
        __syncthreads();
        // P7: y = LN(y + z2 @ W_ca^T + b_ca)   [folded cross-attn, LN fused]
        gemmQ<M_ADDLN>(sZ, g_Wca, g_bca, sY, wid, lane, yn1_g, yn1_b);
        __syncthreads();
        // P8: FFN y hidden
        PAIR(M_GELU, sY, y_ffn_w1, y_ffn_b1, sSA,  sY, y_ffn_w1 + 64*64, y_ffn_b1 + 64, sSB);
        // P9: y = LN(y + [SA|SB] @ w2^T + b2)   [LN fused]
        gemmQ128(sSA, sSB, y_ffn_w2, y_ffn_b2, sY, wid, lane, yn2_g, yn2_b);
        __syncthreads();
    }

    // ---- output: (y @ W_out^T + b_out)[:, 0] ----
    {
        const float4* yp = (const float4*)(sY + eoff);
        float acc = 0.f;
#pragma unroll
        for (int i = 0; i < 8; i++) {
            float4 v = yp[i];
            float4 w = __ldg((const float4*)(W_out + 32 * eh + 4 * i));
            acc = fmaf(v.x, w.x, fmaf(v.y, w.y, fmaf(v.z, w.z, fmaf(v.w, w.w, acc))));
        }
        acc += __shfl_xor_sync(0xFFFFFFFFu, acc, 1);
        int r = row0 + erow;
        if (eh == 0 && r < Btotal) out[r] = acc + __ldg(b_out);
    }
}

extern "C" void kernel_launch(void* const* d_in, const int* in_sizes, int n_in,
                              void* d_out, int out_size)
{
    const float* x        = (const float*)d_in[0];
    const float* W_in     = (const float*)d_in[1];
    const float* b_in     = (const float*)d_in[2];
    const float* g_in     = (const float*)d_in[3];
    const float* be_in    = (const float*)d_in[4];
    const float* z_in_w   = (const float*)d_in[5];
    const float* z_in_b   = (const float*)d_in[6];
    const float* z_out_w  = (const float*)d_in[7];
    const float* z_out_b  = (const float*)d_in[8];
    const float* z_ffn_w1 = (const float*)d_in[9];
    const float* z_ffn_b1 = (const float*)d_in[10];
    const float* z_ffn_w2 = (const float*)d_in[11];
    const float* z_ffn_b2 = (const float*)d_in[12];
    const float* zn1_g    = (const float*)d_in[13];
    const float* zn1_b    = (const float*)d_in[14];
    const float* zn2_g    = (const float*)d_in[15];
    const float* zn2_b    = (const float*)d_in[16];
    const float* y_in_w   = (const float*)d_in[17];
    const float* y_in_b   = (const float*)d_in[18];
    const float* y_out_w  = (const float*)d_in[19];
    const float* y_out_b  = (const float*)d_in[20];
    const float* y_ffn_w1 = (const float*)d_in[21];
    const float* y_ffn_b1 = (const float*)d_in[22];
    const float* y_ffn_w2 = (const float*)d_in[23];
    const float* y_ffn_b2 = (const float*)d_in[24];
    const float* yn1_g    = (const float*)d_in[25];
    const float* yn1_b    = (const float*)d_in[26];
    const float* yn2_g    = (const float*)d_in[27];
    const float* yn2_b    = (const float*)d_in[28];
    const float* W_out    = (const float*)d_in[29];
    const float* b_out    = (const float*)d_in[30];
    float* out = (float*)d_out;

    int B = in_sizes[0] / 200;

    prep_kernel<<<64, 64>>>(y_out_w, y_in_w, y_in_b, y_out_b);

    size_t smem = (size_t)6 * ROWS * ST * sizeof(float);   // 104448 B -> 2 CTAs/SM
    cudaFuncSetAttribute(trm_kernel, cudaFuncAttributeMaxDynamicSharedMemorySize, (int)smem);

    dim3 grid((B + ROWS - 1) / ROWS);
    trm_kernel<<<grid, TPB, smem>>>(x, W_in, b_in, g_in, be_in,
                                    z_in_w, z_in_b, z_out_w, z_out_b,
                                    z_ffn_w1, z_ffn_b1, z_ffn_w2, z_ffn_b2,
                                    zn1_g, zn1_b, zn2_g, zn2_b,
                                    y_ffn_w1, y_ffn_b1, y_ffn_w2, y_ffn_b2,
                                    yn1_g, yn1_b, yn2_g, yn2_b,
                                    W_out, b_out, out, B);
}

// round 13
// speedup vs baseline: 1.2530x; 1.2530x over previous
#include <cuda_runtime.h>

#define TPB    128
#define ROWS   64
#define ST     68          // buffer row stride in floats (68 % 32 == 4 -> conflict-free)
#define NSTEPS 16

__device__ float g_Wca[64 * 64];
__device__ float g_bca[64];

__device__ __forceinline__ float gelu_exact(float v) {
    return 0.5f * v * (1.0f + erff(v * 0.70710678118654752f));
}

// packed fp32x2 FMA: acc.{lo,hi} += a.{lo,hi} * b.{lo,hi}   (FFMA2 on sm_103a)
__device__ __forceinline__ void ffma2(unsigned long long& acc,
                                      unsigned long long a, unsigned long long b) {
    asm("fma.rn.f32x2 %0, %1, %2, %0;" : "+l"(acc) : "l"(a), "l"(b));
}
// horizontal reduce of a packed pair
__device__ __forceinline__ float pairsum(unsigned long long v) {
    float lo, hi;
    asm("mov.b64 {%0, %1}, %2;" : "=f"(lo), "=f"(hi) : "l"(v));
    return lo + hi;
}

// ---------------------------------------------------------------------------
// gemm32: ONE WARP computes rows 0..63 x cols [32ch, 32ch+32); 8x8 per-lane
// tile, k-packed FFMA2 accumulators. mode: 0=store, 1=gelu+store, 2=add-dest.
// ---------------------------------------------------------------------------
__device__ __forceinline__ void gemm32(const float* sIn, const float* __restrict__ W,
                                       const float* __restrict__ bias, float* sOut,
                                       int mode, int ch, int lane)
{
    const int ly = lane & 7, lx = lane >> 3;
    const int c0 = 32 * ch + 8 * lx;
    unsigned long long acc[8][8];
#pragma unroll
    for (int i = 0; i < 8; i++)
#pragma unroll
        for (int j = 0; j < 8; j++) acc[i][j] = 0ull;

    const float* ip = sIn + ly * ST;
    const float* wp = W + c0 * 64;

#pragma unroll 1
    for (int k = 0; k < 64; k += 4) {
        ulonglong2 w[8];
#pragma unroll
        for (int j = 0; j < 8; j++) w[j] = __ldg((const ulonglong2*)(wp + j * 64 + k));
#pragma unroll
        for (int i = 0; i < 8; i++) {
            ulonglong2 b = *(const ulonglong2*)(ip + i * (8 * ST) + k);
#pragma unroll
            for (int j = 0; j < 8; j++) {
                ffma2(acc[i][j], w[j].x, b.x);
                ffma2(acc[i][j], w[j].y, b.y);
            }
        }
    }

    float bb[8];
    if (bias) {
#pragma unroll
        for (int j = 0; j < 8; j++) bb[j] = __ldg(bias + c0 + j);
    } else {
#pragma unroll
        for (int j = 0; j < 8; j++) bb[j] = 0.f;
    }
#pragma unroll
    for (int i = 0; i < 8; i++) {
        float* op = sOut + (ly + 8 * i) * ST + c0;
#pragma unroll
        for (int q = 0; q < 2; q++) {
            float4 v;
            v.x = pairsum(acc[i][4*q+0]) + bb[4*q+0];
            v.y = pairsum(acc[i][4*q+1]) + bb[4*q+1];
            v.z = pairsum(acc[i][4*q+2]) + bb[4*q+2];
            v.w = pairsum(acc[i][4*q+3]) + bb[4*q+3];
            if (mode == 1) {
                v.x = gelu_exact(v.x); v.y = gelu_exact(v.y);
                v.z = gelu_exact(v.z); v.w = gelu_exact(v.w);
            } else if (mode == 2) {
                float4 d = *(const float4*)(op + 4*q);
                v.x += d.x; v.y += d.y; v.z += d.z; v.w += d.w;
            }
            *(float4*)(op + 4*q) = v;
        }
    }
}

// ---------------------------------------------------------------------------
// gemm16: 4-WARP single unit; warp w computes cols [16w, 16w+16).
// ---------------------------------------------------------------------------
__device__ __forceinline__ void gemm16(const float* sIn, const float* __restrict__ W,
                                       int wrs, int kof,
                                       const float* __restrict__ bias, float* sOut,
                                       int mode, int w, int lane)
{
    const int ly = lane & 7, lx = (lane >> 3) & 3;
    const int c0 = 16 * w + 4 * lx;
    unsigned long long acc[8][4];
#pragma unroll
    for (int i = 0; i < 8; i++)
#pragma unroll
        for (int j = 0; j < 4; j++) acc[i][j] = 0ull;

    const float* ip = sIn + ly * ST;
    const float* wp = W + c0 * wrs + kof;

#pragma unroll 1
    for (int k = 0; k < 64; k += 4) {
        ulonglong2 w4[4];
#pragma unroll
        for (int j = 0; j < 4; j++) w4[j] = __ldg((const ulonglong2*)(wp + j * wrs + k));
#pragma unroll
        for (int i = 0; i < 8; i++) {
            ulonglong2 b = *(const ulonglong2*)(ip + i * (8 * ST) + k);
#pragma unroll
            for (int j = 0; j < 4; j++) {
                ffma2(acc[i][j], w4[j].x, b.x);
                ffma2(acc[i][j], w4[j].y, b.y);
            }
        }
    }

    float4 bb;
    if (bias) bb = __ldg((const float4*)(bias + c0));
    else      bb = make_float4(0.f, 0.f, 0.f, 0.f);
#pragma unroll
    for (int i = 0; i < 8; i++) {
        float* op = sOut + (ly + 8 * i) * ST + c0;
        float4 v;
        v.x = pairsum(acc[i][0]) + bb.x; v.y = pairsum(acc[i][1]) + bb.y;
        v.z = pairsum(acc[i][2]) + bb.z; v.w = pairsum(acc[i][3]) + bb.w;
        if (mode == 1) {
            v.x = gelu_exact(v.x); v.y = gelu_exact(v.y);
            v.z = gelu_exact(v.z); v.w = gelu_exact(v.w);
        } else if (mode == 2) {
            float4 d = *(const float4*)op;
            v.x += d.x; v.y += d.y; v.z += d.z; v.w += d.w;
        }
        *(float4*)op = v;
    }
}

// Prologue: 4-warp, K=200, input rows from GLOBAL x (row stride 200).
__device__ __forceinline__ void gemm200(const float* __restrict__ gIn,
                                        const float* __restrict__ W,
                                        const float* __restrict__ bias, float* sOut,
                                        int w, int lane)
{
    const int ly = lane & 7, lx = (lane >> 3) & 3;
    const int c0 = 16 * w + 4 * lx;
    unsigned long long acc[8][4];
#pragma unroll
    for (int i = 0; i < 8; i++)
#pragma unroll
        for (int j = 0; j < 4; j++) acc[i][j] = 0ull;

    const float* ip = gIn + (size_t)ly * 200;
    const float* wp = W + c0 * 200;

#pragma unroll 1
    for (int k = 0; k < 200; k += 4) {
        ulonglong2 w4[4];
#pragma unroll
        for (int j = 0; j < 4; j++) w4[j] = __ldg((const ulonglong2*)(wp + j * 200 + k));
#pragma unroll
        for (int i = 0; i < 8; i++) {
            ulonglong2 b = __ldg((const ulonglong2*)(ip + (size_t)i * 8 * 200 + k));
#pragma unroll
            for (int j = 0; j < 4; j++) {
                ffma2(acc[i][j], w4[j].x, b.x);
                ffma2(acc[i][j], w4[j].y, b.y);
            }
        }
    }
    float4 bb = __ldg((const float4*)(bias + c0));
#pragma unroll
    for (int i = 0; i < 8; i++) {
        float* op = sOut + (ly + 8 * i) * ST + c0;
        float4 v;
        v.x = pairsum(acc[i][0]) + bb.x; v.y = pairsum(acc[i][1]) + bb.y;
        v.z = pairsum(acc[i][2]) + bb.z; v.w = pairsum(acc[i][3]) + bb.w;
        *(float4*)op = v;
    }
}

// LayerNorm, 2 threads per row: p = row base + 32*h; pair-reduce via shfl.bfly(1).
__device__ __forceinline__ void ln2(float* p, const float* __restrict__ g,
                                    const float* __restrict__ b, bool dogelu, int h)
{
    float4 v[8];
#pragma unroll
    for (int i = 0; i < 8; i++) v[i] = *(const float4*)(p + 4 * i);
    float s = 0.f;
#pragma unroll
    for (int i = 0; i < 8; i++) s += (v[i].x + v[i].y) + (v[i].z + v[i].w);
    s += __shfl_xor_sync(0xFFFFFFFFu, s, 1);
    float m = s * (1.0f / 64.0f);
    float qv = 0.f;
#pragma unroll
    for (int i = 0; i < 8; i++) {
        float dx = v[i].x - m, dy = v[i].y - m, dz = v[i].z - m, dw = v[i].w - m;
        qv = fmaf(dx, dx, qv); qv = fmaf(dy, dy, qv);
        qv = fmaf(dz, dz, qv); qv = fmaf(dw, dw, qv);
    }
    qv += __shfl_xor_sync(0xFFFFFFFFu, qv, 1);
    float inv = rsqrtf(qv * (1.0f / 64.0f) + 1e-5f);
#pragma unroll
    for (int i = 0; i < 8; i++) {
        float4 gg = __ldg((const float4*)(g + 32 * h + 4 * i));
        float4 bb = __ldg((const float4*)(b + 32 * h + 4 * i));
        float4 r;
        r.x = fmaf((v[i].x - m) * inv, gg.x, bb.x);
        r.y = fmaf((v[i].y - m) * inv, gg.y, bb.y);
        r.z = fmaf((v[i].z - m) * inv, gg.z, bb.z);
        r.w = fmaf((v[i].w - m) * inv, gg.w, bb.w);
        if (dogelu) {
            r.x = gelu_exact(r.x); r.y = gelu_exact(r.y);
            r.z = gelu_exact(r.z); r.w = gelu_exact(r.w);
        }
        *(float4*)(p + 4 * i) = r;
    }
}

// prep: W_ca = y_out_w @ Wvy ; b_ca = y_out_w @ bvy + y_out_b
__global__ void prep_kernel(const float* __restrict__ y_out_w,
                            const float* __restrict__ y_in_w,
                            const float* __restrict__ y_in_b,
                            const float* __restrict__ y_out_b)
{
    int i = blockIdx.x;
    int k = threadIdx.x;
    const float* Wvy = y_in_w + 128 * 64;
    float a = 0.f;
    for (int j = 0; j < 64; j++)
        a = fmaf(y_out_w[i * 64 + j], Wvy[j * 64 + k], a);
    g_Wca[i * 64 + k] = a;
    if (k == 0) {
        float b = y_out_b[i];
        for (int j = 0; j < 64; j++) b = fmaf(y_out_w[i * 64 + j], y_in_b[128 + j], b);
        g_bca[i] = b;
    }
}

// pair-phase macro: warps 0,1 -> unit A (col halves 0/1); warps 2,3 -> unit B.
#define PAIR(inA, WA, bA, oA, mA, inB, WB, bB, oB, mB) do {            \
    const float* gi; const float* gw; const float* gb; float* go; int gm; \
    if (wid < 2) { gi = (inA); gw = (WA); gb = (bA); go = (oA); gm = (mA); } \
    else         { gi = (inB); gw = (WB); gb = (bB); go = (oB); gm = (mB); } \
    gemm32(gi, gw, gb, go, gm, wid & 1, lane);                          \
    __syncthreads(); } while (0)

#define SINGLE(in, W, wrs, kof, b, o, m) do {                          \
    gemm16((in), (W), (wrs), (kof), (b), (o), (m), wid, lane);         \
    __syncthreads(); } while (0)

__global__ void __launch_bounds__(TPB, 2)
trm_kernel(const float* __restrict__ x,
           const float* __restrict__ W_in,     const float* __restrict__ b_in,
           const float* __restrict__ g_in,     const float* __restrict__ be_in,
           const float* __restrict__ z_in_w,   const float* __restrict__ z_in_b,
           const float* __restrict__ z_out_w,  const float* __restrict__ z_out_b,
           const float* __restrict__ z_ffn_w1, const float* __restrict__ z_ffn_b1,
           const float* __restrict__ z_ffn_w2, const float* __restrict__ z_ffn_b2,
           const float* __restrict__ zn1_g,    const float* __restrict__ zn1_b,
           const float* __restrict__ zn2_g,    const float* __restrict__ zn2_b,
           const float* __restrict__ y_ffn_w1, const float* __restrict__ y_ffn_b1,
           const float* __restrict__ y_ffn_w2, const float* __restrict__ y_ffn_b2,
           const float* __restrict__ yn1_g,    const float* __restrict__ yn1_b,
           const float* __restrict__ yn2_g,    const float* __restrict__ yn2_b,
           const float* __restrict__ W_out,    const float* __restrict__ b_out,
           float* __restrict__ out, int Btotal)
{
    extern __shared__ float sm[];
    float* sKX = sm + 0 * ROWS * ST;
    float* sVX = sm + 1 * ROWS * ST;
    float* sY  = sm + 2 * ROWS * ST;
    float* sZ  = sm + 3 * ROWS * ST;
    float* sSA = sm + 4 * ROWS * ST;
    float* sSB = sm + 5 * ROWS * ST;

    const int tid  = threadIdx.x;
    const int wid  = tid >> 5;
    const int lane = tid & 31;
    const int row0 = blockIdx.x * ROWS;
    const int erow = tid >> 1, eh = tid & 1;   // elementwise: 2 threads/row
    const int eoff = erow * ST + 32 * eh;

    const float* Wq = z_in_w;
    const float* Wk = z_in_w + 64 * 64;
    const float* Wv = z_in_w + 128 * 64;
    const float* bq = z_in_b;
    const float* bk = z_in_b + 64;
    const float* bv = z_in_b + 128;

    // ---- prologue: x_proj = gelu(LN(x @ W_in^T + b_in)) -> SA ----
    gemm200(x + (size_t)row0 * 200, W_in, b_in, sSA, wid, lane);
    __syncthreads();
    ln2(sSA + eoff, g_in, be_in, true, eh);
    __syncthreads();
    // kx = xp@Wk^T+bk  ||  vx = xp@Wv^T+bv
    PAIR(sSA, Wk, bk, sKX, 0,  sSA, Wv, bv, sVX, 0);
    // zero y, z (all 128 threads)
    {
        float* yp = sY + eoff;
        float* zp = sZ + eoff;
        const float4 zz = make_float4(0.f, 0.f, 0.f, 0.f);
#pragma unroll
        for (int i = 0; i < 8; i++) { *(float4*)(yp + 4*i) = zz; *(float4*)(zp + 4*i) = zz; }
    }
    __syncthreads();

    // ---- 16 recursion steps ----
#pragma unroll 1
    for (int s = 0; s < NSTEPS; s++) {
        float qv[32];
        float s0[2], s2[2], wa0[2], wa1[2], wa2[2];

        // P1: q(z) -> SA  ||  k(z) -> SB
        PAIR(sZ, Wq, bq, sSA, 0,  sZ, Wk, bk, sSB, 0);
        // E1: load q half to regs; s0 = q.kx, s2 = q.kz
        {
            const float4* qp  = (const float4*)(sSA + eoff);
            const float4* kxp = (const float4*)(sKX + eoff);
            const float4* kzp = (const float4*)(sSB + eoff);
            s0[0] = s0[1] = s2[0] = s2[1] = 0.f;
#pragma unroll
            for (int i = 0; i < 8; i++) {
                float4 t = qp[i];
                qv[4*i] = t.x; qv[4*i+1] = t.y; qv[4*i+2] = t.z; qv[4*i+3] = t.w;
                int hh = i >> 2;
                float4 a = kxp[i];
                float4 c = kzp[i];
                s0[hh] = fmaf(t.x, a.x, fmaf(t.y, a.y, fmaf(t.z, a.z, fmaf(t.w, a.w, s0[hh]))));
                s2[hh] = fmaf(t.x, c.x, fmaf(t.y, c.y, fmaf(t.z, c.z, fmaf(t.w, c.w, s2[hh]))));
            }
        }
        __syncthreads();
        // P2: k(y) -> SB (q stays in registers)
        SINGLE(sY, Wk, 64, 0, bk, sSB, 0);
        // E2: s1 = q.ky ; softmax
        {
            const float4* kyp = (const float4*)(sSB + eoff);
            float s1[2] = {0.f, 0.f};
#pragma unroll
            for (int i = 0; i < 8; i++) {
                int hh = i >> 2;
                float4 a = kyp[i];
                s1[hh] = fmaf(qv[4*i], a.x, fmaf(qv[4*i+1], a.y,
                         fmaf(qv[4*i+2], a.z, fmaf(qv[4*i+3], a.w, s1[hh]))));
            }
#pragma unroll
            for (int hh = 0; hh < 2; hh++) {
                float a0 = s0[hh] * 0.25f, a1 = s1[hh] * 0.25f, a2 = s2[hh] * 0.25f;
                float mx = fmaxf(a0, fmaxf(a1, a2));
                float e0 = __expf(a0 - mx), e1 = __expf(a1 - mx), e2 = __expf(a2 - mx);
                float rs = 1.0f / (e0 + e1 + e2);
                wa0[hh] = e0 * rs; wa1[hh] = e1 * rs; wa2[hh] = e2 * rs;
            }
        }
        __syncthreads();
        // P3: v(y) -> SA  ||  v(z) -> SB
        PAIR(sY, Wv, bv, sSA, 0,  sZ, Wv, bv, sSB, 0);
        // E3: SA := wa0*vx + wa1*vy + wa2*vz
        {
            float* sap = sSA + eoff;
            const float4* sbp = (const float4*)(sSB + eoff);
            const float4* vxp = (const float4*)(sVX + eoff);
#pragma unroll
            for (int i = 0; i < 8; i++) {
                int hh = i >> 2;
                float4 a = vxp[i];
                float4 b2 = *(const float4*)(sap + 4*i);
                float4 c = sbp[i];
                float4 o;
                o.x = wa0[hh]*a.x + wa1[hh]*b2.x + wa2[hh]*c.x;
                o.y = wa0[hh]*a.y + wa1[hh]*b2.y + wa2[hh]*c.y;
                o.z = wa0[hh]*a.z + wa1[hh]*b2.z + wa2[hh]*c.z;
                o.w = wa0[hh]*a.w + wa1[hh]*b2.w + wa2[hh]*c.w;
                *(float4*)(sap + 4*i) = o;
            }
        }
        __syncthreads();
        // P4: z += SA @ z_out_w^T + z_out_b ; LN zn1
        SINGLE(sSA, z_out_w, 64, 0, z_out_b, sZ, 2);
        ln2(sZ + eoff, zn1_g, zn1_b, false, eh);
        __syncthreads();
        // P5: FFN z hidden: gelu -> SA (dims 0-63) || SB (dims 64-127)
        PAIR(sZ, z_ffn_w1, z_ffn_b1, sSA, 1,  sZ, z_ffn_w1 + 64*64, z_ffn_b1 + 64, sSB, 1);
        // P6: z += [SA|SB] @ w2^T + b2 ; LN zn2
        gemm16(sSA, z_ffn_w2, 128, 0,  z_ffn_b2, sZ, 2, wid, lane);
        gemm16(sSB, z_ffn_w2, 128, 64, (const float*)0, sZ, 2, wid, lane);
        __syncthreads();
        ln2(sZ + eoff, zn2_g, zn2_b, false, eh);
        __syncthreads();
        // P7: y += z2 @ W_ca^T + b_ca ; LN yn1   [folded cross-attention]
        SINGLE(sZ, g_Wca, 64, 0, g_bca, sY, 2);
        ln2(sY + eoff, yn1_g, yn1_b, false, eh);
        __syncthreads();
        // P8: FFN y hidden
        PAIR(sY, y_ffn_w1, y_ffn_b1, sSA, 1,  sY, y_ffn_w1 + 64*64, y_ffn_b1 + 64, sSB, 1);
        // P9: y += [SA|SB] @ w2^T + b2 ; LN yn2
        gemm16(sSA, y_ffn_w2, 128, 0,  y_ffn_b2, sY, 2, wid, lane);
        gemm16(sSB, y_ffn_w2, 128, 64, (const float*)0, sY, 2, wid, lane);
        __syncthreads();
        ln2(sY + eoff, yn2_g, yn2_b, false, eh);
        __syncthreads();
    }

    // ---- output: (y @ W_out^T + b_out)[:, 0] ----
    {
        const float4* yp = (const float4*)(sY + eoff);
        float acc = 0.f;
#pragma unroll
        for (int i = 0; i < 8; i++) {
            float4 v = yp[i];
            float4 w = __ldg((const float4*)(W_out + 32 * eh + 4 * i));
            acc = fmaf(v.x, w.x, fmaf(v.y, w.y, fmaf(v.z, w.z, fmaf(v.w, w.w, acc))));
        }
        acc += __shfl_xor_sync(0xFFFFFFFFu, acc, 1);
        int r = row0 + erow;
        if (eh == 0 && r < Btotal) out[r] = acc + __ldg(b_out);
    }
}

extern "C" void kernel_launch(void* const* d_in, const int* in_sizes, int n_in,
                              void* d_out, int out_size)
{
    const float* x        = (const float*)d_in[0];
    const float* W_in     = (const float*)d_in[1];
    const float* b_in     = (const float*)d_in[2];
    const float* g_in     = (const float*)d_in[3];
    const float* be_in    = (const float*)d_in[4];
    const float* z_in_w   = (const float*)d_in[5];
    const float* z_in_b   = (const float*)d_in[6];
    const float* z_out_w  = (const float*)d_in[7];
    const float* z_out_b  = (const float*)d_in[8];
    const float* z_ffn_w1 = (const float*)d_in[9];
    const float* z_ffn_b1 = (const float*)d_in[10];
    const float* z_ffn_w2 = (const float*)d_in[11];
    const float* z_ffn_b2 = (const float*)d_in[12];
    const float* zn1_g    = (const float*)d_in[13];
    const float* zn1_b    = (const float*)d_in[14];
    const float* zn2_g    = (const float*)d_in[15];
    const float* zn2_b    = (const float*)d_in[16];
    const float* y_in_w   = (const float*)d_in[17];
    const float* y_in_b   = (const float*)d_in[18];
    const float* y_out_w  = (const float*)d_in[19];
    const float* y_out_b  = (const float*)d_in[20];
    const float* y_ffn_w1 = (const float*)d_in[21];
    const float* y_ffn_b1 = (const float*)d_in[22];
    const float* y_ffn_w2 = (const float*)d_in[23];
    const float* y_ffn_b2 = (const float*)d_in[24];
    const float* yn1_g    = (const float*)d_in[25];
    const float* yn1_b    = (const float*)d_in[26];
    const float* yn2_g    = (const float*)d_in[27];
    const float* yn2_b    = (const float*)d_in[28];
    const float* W_out    = (const float*)d_in[29];
    const float* b_out    = (const float*)d_in[30];
    float* out = (float*)d_out;

    int B = in_sizes[0] / 200;

    prep_kernel<<<64, 64>>>(y_out_w, y_in_w, y_in_b, y_out_b);

    size_t smem = (size_t)6 * ROWS * ST * sizeof(float);   // 104448 B -> 2 CTAs/SM
    cudaFuncSetAttribute(trm_kernel, cudaFuncAttributeMaxDynamicSharedMemorySize, (int)smem);

    dim3 grid((B + ROWS - 1) / ROWS);
    trm_kernel<<<grid, TPB, smem>>>(x, W_in, b_in, g_in, be_in,
                                    z_in_w, z_in_b, z_out_w, z_out_b,
                                    z_ffn_w1, z_ffn_b1, z_ffn_w2, z_ffn_b2,
                                    zn1_g, zn1_b, zn2_g, zn2_b,
                                    y_ffn_w1, y_ffn_b1, y_ffn_w2, y_ffn_b2,
                                    yn1_g, yn1_b, yn2_g, yn2_b,
                                    W_out, b_out, out, B);
}